// round 13
// baseline (speedup 1.0000x reference)
#include <cuda_runtime.h>
#include <cuda_fp16.h>
#include <cstdint>

#define MAXN 100000
#define MAXE 1000000
#define NGRAPH 1024

// ---------------- static scratch (allocation-free contract) ----------------
__device__ __align__(16) float  g_h[MAXN * 64];     // embedded features (fp32)
__device__ __align__(16) __half g_t16[MAXN * 64];   // dinv * (h @ W), fp16 payload
__device__ __align__(16) float  g_agg[MAXN * 64];   // aggregated features (fp32)
__device__ __align__(16) float  g_hout[MAXN * 64];  // final node features (fallback)
__device__ float g_dinv[MAXN];
__device__ int   g_cnt[MAXN];
__device__ int   g_off[MAXN];
__device__ int   g_cur[MAXN];
__device__ int   g_bsum[256];
__device__ int   g_esrc[MAXE];
__device__ int   g_is64;

__device__ __forceinline__ int idx_at(const void* p, long long i) {
    return g_is64 ? (int)((const long long*)p)[i] : ((const int*)p)[i];
}

// load a half2 word from global and widen to float2 (legal lvalue handling)
__device__ __forceinline__ float2 ld_h2f2(const unsigned* p) {
    unsigned u = __ldg(p);
    __half2 h;
    *(unsigned*)&h = u;
    return __half22float2(h);
}

// packed f32x2 helpers
__device__ __forceinline__ unsigned long long pack2(float lo, float hi) {
    unsigned long long r;
    asm("mov.b64 %0, {%1, %2};" : "=l"(r) : "f"(lo), "f"(hi));
    return r;
}
__device__ __forceinline__ void unpack2(unsigned long long v, float& lo, float& hi) {
    asm("mov.b64 {%0, %1}, %2;" : "=f"(lo), "=f"(hi) : "l"(v));
}
#define FMA2(acc, a, b) \
    asm("fma.rn.f32x2 %0, %1, %2, %0;" : "+l"(acc) : "l"(a), "l"(b))

// ---------------- prep 1: zero cnt + dtype probe ----------------
__global__ void k_prep(const int* __restrict__ batch_w, int N) {
    int i = blockIdx.x * blockDim.x + threadIdx.x;
    if (i < N) g_cnt[i] = 0;
    if (blockIdx.x == 0 && threadIdx.x == 0) {
        int nz = 0;
        for (int k = 1; k <= 64; k++) {
            int idx = (N & ~1) - 2 * k + 1;
            if (idx > 0 && idx < N) nz |= batch_w[idx];
        }
        g_is64 = (nz == 0) ? 1 : 0;
    }
}

__global__ void k_count(const void* __restrict__ ei, int E, int N) {
    int e = blockIdx.x * blockDim.x + threadIdx.x;
    if (e >= E) return;
    unsigned d = (unsigned)idx_at(ei, (long long)E + e);
    if (d < (unsigned)N) atomicAdd(&g_cnt[d], 1);
}

// scan pass 1 (+ dinv)
__global__ void k_scan1(int N) {
    __shared__ int s[1024];
    int tid = threadIdx.x;
    int i = blockIdx.x * 1024 + tid;
    int v = (i < N) ? g_cnt[i] : 0;
    if (i < N) g_dinv[i] = rsqrtf((float)(v + 1));
    s[tid] = v;
    __syncthreads();
#pragma unroll
    for (int off = 1; off < 1024; off <<= 1) {
        int t = (tid >= off) ? s[tid - off] : 0;
        __syncthreads();
        s[tid] += t;
        __syncthreads();
    }
    if (i < N) g_off[i] = s[tid] - v;
    if (tid == 1023) g_bsum[blockIdx.x] = s[1023];
}

// scan pass 2+3 merged
__global__ void k_scan23(int N, int nb) {
    __shared__ int s[256];
    int tid = threadIdx.x;
    if (tid < 256) s[tid] = (tid < nb) ? g_bsum[tid] : 0;
    __syncthreads();
#pragma unroll
    for (int off = 1; off < 256; off <<= 1) {
        int t = 0;
        if (tid < 256 && tid >= off) t = s[tid - off];
        __syncthreads();
        if (tid < 256) s[tid] += t;
        __syncthreads();
    }
    int i = blockIdx.x * 1024 + tid;
    if (i < N) {
        int pre = (blockIdx.x > 0) ? s[blockIdx.x - 1] : 0;
        int o = g_off[i] + pre;
        g_off[i] = o;
        g_cur[i] = o;
    }
}

__global__ void k_bucket(const void* __restrict__ ei, int E, int N) {
    int e = blockIdx.x * blockDim.x + threadIdx.x;
    if (e >= E) return;
    unsigned s = (unsigned)idx_at(ei, e);
    unsigned d = (unsigned)idx_at(ei, (long long)E + e);
    if (s >= (unsigned)N || d >= (unsigned)N) return;
    int pos = atomicAdd(&g_cur[d], 1);
    if ((unsigned)pos >= (unsigned)E) return;
    g_esrc[pos] = (int)s;
}

// ---------------- register-blocked GEMM with packed f32x2 FMAs ----------------
// MODE 0: in = xin,  out g_h (fp32)  = relu(acc + bias_out)
// MODE 1: in = g_h,  out g_t16 (fp16) = acc * dinv[row]
// MODE 2: in = relu(g_agg + bias_in), out g_t16 = acc * dinv[row]
template <int K, int MODE>
__global__ __launch_bounds__(256) void k_gemm(
    const float* __restrict__ xin, const float* __restrict__ W,
    const float* __restrict__ bias_in, const float* __restrict__ bias_out, int N)
{
    __shared__ float in_s[128 * 33];
    __shared__ float W_s[32 * 64];

    const int tid = threadIdx.x;
    const int l   = tid & 31;
    const int cg  = tid >> 5;
    const int rowBase = blockIdx.x * 128;

    const float* in;
    if (MODE == 0) in = xin;
    else if (MODE == 1) in = g_h;
    else in = g_agg;

    unsigned long long acc[4][4];
#pragma unroll
    for (int i = 0; i < 4; i++)
#pragma unroll
        for (int j = 0; j < 4; j++) acc[i][j] = 0ull;

    const int NCHUNK = K / 32;
#pragma unroll
    for (int ch = 0; ch < NCHUNK; ch++) {
        for (int idx = tid; idx < 128 * 8; idx += 256) {
            int r  = idx >> 3;
            int c4 = (idx & 7) * 4;
            int gr = rowBase + r;
            int gc = ch * 32 + c4;
            float4 v = make_float4(0.f, 0.f, 0.f, 0.f);
            if (gr < N) v = *(const float4*)(in + (size_t)gr * K + gc);
            if (MODE == 2) {
                v.x = fmaxf(v.x + __ldg(&bias_in[gc + 0]), 0.f);
                v.y = fmaxf(v.y + __ldg(&bias_in[gc + 1]), 0.f);
                v.z = fmaxf(v.z + __ldg(&bias_in[gc + 2]), 0.f);
                v.w = fmaxf(v.w + __ldg(&bias_in[gc + 3]), 0.f);
            }
            float* p = &in_s[r * 33 + c4];
            p[0] = v.x; p[1] = v.y; p[2] = v.z; p[3] = v.w;
        }
        for (int idx = tid; idx < 32 * 16; idx += 256) {
            int kr = idx >> 4;
            int c4 = (idx & 15) * 4;
            *(float4*)(&W_s[kr * 64 + c4]) =
                *(const float4*)(W + (size_t)(ch * 32 + kr) * 64 + c4);
        }
        __syncthreads();

#pragma unroll 8
        for (int k = 0; k < 32; k++) {
            float a0 = in_s[(l      ) * 33 + k];
            float a1 = in_s[(l + 32 ) * 33 + k];
            float a2 = in_s[(l + 64 ) * 33 + k];
            float a3 = in_s[(l + 96 ) * 33 + k];
            unsigned long long ap0 = pack2(a0, a0);
            unsigned long long ap1 = pack2(a1, a1);
            unsigned long long ap2 = pack2(a2, a2);
            unsigned long long ap3 = pack2(a3, a3);
            const ulonglong2* wp = (const ulonglong2*)(&W_s[k * 64 + cg * 8]);
            ulonglong2 wv0 = wp[0], wv1 = wp[1];
            unsigned long long w01 = wv0.x, w23 = wv0.y, w45 = wv1.x, w67 = wv1.y;
            FMA2(acc[0][0], ap0, w01); FMA2(acc[0][1], ap0, w23);
            FMA2(acc[0][2], ap0, w45); FMA2(acc[0][3], ap0, w67);
            FMA2(acc[1][0], ap1, w01); FMA2(acc[1][1], ap1, w23);
            FMA2(acc[1][2], ap1, w45); FMA2(acc[1][3], ap1, w67);
            FMA2(acc[2][0], ap2, w01); FMA2(acc[2][1], ap2, w23);
            FMA2(acc[2][2], ap2, w45); FMA2(acc[2][3], ap2, w67);
            FMA2(acc[3][0], ap3, w01); FMA2(acc[3][1], ap3, w23);
            FMA2(acc[3][2], ap3, w45); FMA2(acc[3][3], ap3, w67);
        }
        __syncthreads();
    }

#pragma unroll
    for (int i = 0; i < 4; i++) {
        int gr = rowBase + l + 32 * i;
        if (gr >= N) continue;
        float v[8];
#pragma unroll
        for (int j = 0; j < 4; j++)
            unpack2(acc[i][j], v[j * 2], v[j * 2 + 1]);
        if (MODE == 0) {
#pragma unroll
            for (int j = 0; j < 8; j++)
                v[j] = fmaxf(v[j] + __ldg(&bias_out[cg * 8 + j]), 0.f);
            float4* tp = (float4*)(g_h + (size_t)gr * 64 + cg * 8);
            tp[0] = make_float4(v[0], v[1], v[2], v[3]);
            tp[1] = make_float4(v[4], v[5], v[6], v[7]);
        } else {
            float dv = __ldg(&g_dinv[gr]);
            __half2 hh[4];
#pragma unroll
            for (int j = 0; j < 4; j++)
                hh[j] = __floats2half2_rn(v[j * 2] * dv, v[j * 2 + 1] * dv);
            *(uint4*)(g_t16 + (size_t)gr * 64 + cg * 8) = *(uint4*)hh;
        }
    }
}

// ---------------- CSR gather-aggregate: ONE WARP PER NODE ----------------
// Lane owns features {2*lane, 2*lane+1} as one half2 word (4 B); a full row
// gather is one coalesced 128 B warp load. Index load is warp-uniform.
// agg[n] = dinv[n] * ( t'[n] + sum_e t'[src_e] )
template <bool FINAL>
__global__ __launch_bounds__(256) void k_agg(
    int N, int E,
    const float* __restrict__ b2, const float* __restrict__ W_tgt,
    const float* __restrict__ b_tgt, float* out_tgt, float* hdst)
{
    int n = (blockIdx.x * blockDim.x + threadIdx.x) >> 5;
    int lane = threadIdx.x & 31;
    if (n >= N) return;

    const unsigned* t2 = (const unsigned*)g_t16;   // row = 32 half2 words

    float2 acc = ld_h2f2(t2 + (size_t)n * 32 + lane);

    int beg = __ldg(&g_off[n]);
    int end = beg + __ldg(&g_cnt[n]);
    if (beg < 0) beg = 0;
    if (end > E) end = E;

    int e = beg;
    for (; e + 3 < end; e += 4) {
        unsigned s0 = (unsigned)__ldg(&g_esrc[e]);
        unsigned s1 = (unsigned)__ldg(&g_esrc[e + 1]);
        unsigned s2 = (unsigned)__ldg(&g_esrc[e + 2]);
        unsigned s3 = (unsigned)__ldg(&g_esrc[e + 3]);
        float2 f0 = ld_h2f2(t2 + (size_t)s0 * 32 + lane);
        float2 f1 = ld_h2f2(t2 + (size_t)s1 * 32 + lane);
        float2 f2 = ld_h2f2(t2 + (size_t)s2 * 32 + lane);
        float2 f3 = ld_h2f2(t2 + (size_t)s3 * 32 + lane);
        acc.x += (f0.x + f1.x) + (f2.x + f3.x);
        acc.y += (f0.y + f1.y) + (f2.y + f3.y);
    }
    for (; e < end; e++) {
        unsigned s0 = (unsigned)__ldg(&g_esrc[e]);
        float2 f0 = ld_h2f2(t2 + (size_t)s0 * 32 + lane);
        acc.x += f0.x; acc.y += f0.y;
    }

    float dv = __ldg(&g_dinv[n]);
    acc.x *= dv; acc.y *= dv;

    if (!FINAL) {
        *(float2*)(g_agg + (size_t)n * 64 + lane * 2) = acc;
    } else {
        float2 b = __ldg(((const float2*)b2) + lane);
        float h0 = fmaxf(acc.x + b.x, 0.f);
        float h1 = fmaxf(acc.y + b.y, 0.f);
        *(float2*)(hdst + (size_t)n * 64 + lane * 2) = make_float2(h0, h1);
        if (out_tgt) {
            float2 w = __ldg(((const float2*)W_tgt) + lane);
            float p = h0 * w.x + h1 * w.y;
#pragma unroll
            for (int off = 16; off > 0; off >>= 1)
                p += __shfl_down_sync(0xffffffffu, p, off);
            if (lane == 0) out_tgt[n] = p + __ldg(b_tgt);
        }
    }
}

// ---------------- pooling + graph heads; graph bounds via binary search ----------------
__global__ __launch_bounds__(256) void k_logits(
    const void* __restrict__ batch, const float* __restrict__ hsrc,
    const float* __restrict__ W_act, const float* __restrict__ b_act,
    const float* __restrict__ W_atom, const float* __restrict__ b_atom,
    float* out_act, float* out_atom, int N)
{
    int g = blockIdx.x;
    int tid = threadIdx.x;
    int f = tid & 63;
    int sl = tid >> 6;
    __shared__ int bounds[2];
    __shared__ float red[4][64];
    __shared__ float p[64];

    if (tid < 2) {
        int target = g + tid;
        int lo = 0, hi = N;
        while (lo < hi) {
            int mid = (lo + hi) >> 1;
            if (idx_at(batch, mid) < target) lo = mid + 1; else hi = mid;
        }
        bounds[tid] = lo;
    }
    __syncthreads();
    int s0 = bounds[0], s1 = bounds[1];

    float acc = 0.f;
    for (int i = s0 + sl; i < s1; i += 4)
        acc += __ldg(&hsrc[(size_t)i * 64 + f]);
    red[sl][f] = acc;
    __syncthreads();

    if (tid < 64) {
        int c = s1 - s0;
        float total = red[0][f] + red[1][f] + red[2][f] + red[3][f];
        p[f] = (c > 0) ? total / (float)c : 0.0f;
    }
    __syncthreads();

    if (tid < 8) {
        if (out_act) {
            float s = __ldg(&b_act[tid]);
#pragma unroll 8
            for (int k = 0; k < 64; k++) s += p[k] * __ldg(&W_act[k * 8 + tid]);
            out_act[g * 8 + tid] = s;
        }
    } else if (tid < 24) {
        if (out_atom) {
            int jj = tid - 8;
            float s = __ldg(&b_atom[jj]);
#pragma unroll 8
            for (int k = 0; k < 64; k++) s += p[k] * __ldg(&W_atom[k * 16 + jj]);
            out_atom[g * 16 + jj] = s;
        }
    }
}

// ---------------- launch ----------------
extern "C" void kernel_launch(void* const* d_in, const int* in_sizes, int n_in,
                              void* d_out, int out_size)
{
    const float* x       = (const float*)d_in[0];
    const void*  ei      = d_in[1];
    const void*  batch   = d_in[2];
    const float* W_emb   = (const float*)d_in[3];
    const float* b_emb   = (const float*)d_in[4];
    const float* W_convs = (const float*)d_in[5];
    const float* b_convs = (const float*)d_in[6];
    const float* W_act   = (const float*)d_in[7];
    const float* b_act   = (const float*)d_in[8];
    const float* W_tgt   = (const float*)d_in[9];
    const float* b_tgt   = (const float*)d_in[10];
    const float* W_atom  = (const float*)d_in[11];
    const float* b_atom  = (const float*)d_in[12];

    const int N = in_sizes[0] / 32;
    int E = in_sizes[1] / 2;
    if (E > MAXE) E = MAXE;

    const long long szA = (long long)NGRAPH * 8;
    const long long szT = N;
    const long long szM = (long long)NGRAPH * 16;
    const long long szH = (long long)N * 64;

    float* out = (float*)d_out;
    long long cum = 0;
    float* out_act  = nullptr;
    float* out_tgt  = nullptr;
    float* out_atom = nullptr;
    float* out_h    = nullptr;
    if (cum + szA <= out_size) { out_act  = out + cum; cum += szA; }
    if (cum + szT <= out_size) { out_tgt  = out + cum; cum += szT; }
    if (cum + szM <= out_size) { out_atom = out + cum; cum += szM; }
    if (cum + szH <= out_size) { out_h    = out + cum; cum += szH; }

    float* hdst;
    {
        static float* g_hout_ptr = nullptr;
        if (!g_hout_ptr) cudaGetSymbolAddress((void**)&g_hout_ptr, g_hout);
        // float2 stores need 8-B alignment of out_h; fall back if misaligned
        hdst = (out_h && ((((uintptr_t)out_h) & 7) == 0)) ? out_h : g_hout_ptr;
    }

    const int TB = 256;
    const int gN   = (N + TB - 1) / TB;
    const int gE   = (E + TB - 1) / TB;
    const int gRow = (N + 127) / 128;
    const int gN32 = (int)(((long long)N * 32 + TB - 1) / TB);
    const int nb   = (N + 1023) / 1024;

    static cudaStream_t s1 = nullptr;
    static cudaEvent_t evFork = nullptr, evDinv = nullptr, evGemm = nullptr;
    static int streamsOk = -1;
    if (streamsOk < 0) {
        bool ok = (cudaStreamCreateWithFlags(&s1, cudaStreamNonBlocking) == cudaSuccess)
               && (cudaEventCreateWithFlags(&evFork, cudaEventDisableTiming) == cudaSuccess)
               && (cudaEventCreateWithFlags(&evDinv, cudaEventDisableTiming) == cudaSuccess)
               && (cudaEventCreateWithFlags(&evGemm, cudaEventDisableTiming) == cudaSuccess);
        streamsOk = ok ? 1 : 0;
    }

    if (streamsOk) {
        cudaEventRecord(evFork, 0);
        cudaStreamWaitEvent(s1, evFork, 0);
        k_gemm<32, 0><<<gRow, TB, 0, s1>>>(x, W_emb, nullptr, b_emb, N);

        k_prep<<<gN, TB>>>((const int*)batch, N);
        k_count<<<gE, TB>>>(ei, E, N);
        k_scan1<<<nb, 1024>>>(N);
        cudaEventRecord(evDinv, 0);

        cudaStreamWaitEvent(s1, evDinv, 0);
        k_gemm<64, 1><<<gRow, TB, 0, s1>>>(nullptr, W_convs + 0 * 4096, nullptr, nullptr, N);
        cudaEventRecord(evGemm, s1);

        k_scan23<<<nb, 1024>>>(N, nb);
        k_bucket<<<gE, TB>>>(ei, E, N);

        cudaStreamWaitEvent(0, evGemm, 0);
    } else {
        k_prep<<<gN, TB>>>((const int*)batch, N);
        k_count<<<gE, TB>>>(ei, E, N);
        k_scan1<<<nb, 1024>>>(N);
        k_scan23<<<nb, 1024>>>(N, nb);
        k_bucket<<<gE, TB>>>(ei, E, N);
        k_gemm<32, 0><<<gRow, TB>>>(x, W_emb, nullptr, b_emb, N);
        k_gemm<64, 1><<<gRow, TB>>>(nullptr, W_convs + 0 * 4096, nullptr, nullptr, N);
    }

    k_agg<false><<<gN32, TB>>>(N, E, nullptr, nullptr, nullptr, nullptr, nullptr);

    k_gemm<64, 2><<<gRow, TB>>>(nullptr, W_convs + 1 * 4096, b_convs + 0 * 64, nullptr, N);
    k_agg<false><<<gN32, TB>>>(N, E, nullptr, nullptr, nullptr, nullptr, nullptr);

    k_gemm<64, 2><<<gRow, TB>>>(nullptr, W_convs + 2 * 4096, b_convs + 1 * 64, nullptr, N);
    k_agg<true><<<gN32, TB>>>(N, E, b_convs + 2 * 64, W_tgt, b_tgt, out_tgt, hdst);

    k_logits<<<NGRAPH, TB>>>(batch, hdst, W_act, b_act, W_atom, b_atom, out_act, out_atom, N);

    if (hdst != out_h && out_h) {
        cudaMemcpyAsync(out_h, hdst, (size_t)N * 64 * sizeof(float),
                        cudaMemcpyDeviceToDevice, 0);
    }
}

// round 14
// speedup vs baseline: 1.1433x; 1.1433x over previous
#include <cuda_runtime.h>
#include <cuda_fp16.h>
#include <cstdint>

#define MAXN 100000
#define MAXE 1000000
#define NGRAPH 1024

// ---------------- static scratch (allocation-free contract) ----------------
__device__ __align__(16) float  g_h[MAXN * 64];      // embedded features (fp32)
__device__ __align__(16) __half g_t16[MAXN * 64];    // dinv * (h @ W), fp16 payload
__device__ __align__(16) __half g_agg16[MAXN * 64];  // aggregated features (fp16)
__device__ __align__(16) float  g_hout[MAXN * 64];   // final node features (fallback)
__device__ float g_dinv[MAXN];
__device__ int   g_cnt[MAXN];
__device__ int   g_off[MAXN];
__device__ int   g_cur[MAXN];
__device__ int   g_bsum[256];
__device__ int   g_esrc[MAXE];
__device__ int   g_is64;

__device__ __forceinline__ int idx_at(const void* p, long long i) {
    return g_is64 ? (int)((const long long*)p)[i] : ((const int*)p)[i];
}

// packed f32x2 helpers
__device__ __forceinline__ unsigned long long pack2(float lo, float hi) {
    unsigned long long r;
    asm("mov.b64 %0, {%1, %2};" : "=l"(r) : "f"(lo), "f"(hi));
    return r;
}
__device__ __forceinline__ void unpack2(unsigned long long v, float& lo, float& hi) {
    asm("mov.b64 {%0, %1}, %2;" : "=f"(lo), "=f"(hi) : "l"(v));
}
#define FMA2(acc, a, b) \
    asm("fma.rn.f32x2 %0, %1, %2, %0;" : "+l"(acc) : "l"(a), "l"(b))

// widen 8 packed halves (uint4) into 4 float2 accum adds
__device__ __forceinline__ void acc_half8(float2* a, uint4 u) {
    __half2 hp[4];
    *(uint4*)hp = u;
#pragma unroll
    for (int j = 0; j < 4; j++) {
        float2 f = __half22float2(hp[j]);
        a[j].x += f.x; a[j].y += f.y;
    }
}

// ---------------- prep 1: zero cnt + dtype probe ----------------
__global__ void k_prep(const int* __restrict__ batch_w, int N) {
    int i = blockIdx.x * blockDim.x + threadIdx.x;
    if (i < N) g_cnt[i] = 0;
    if (blockIdx.x == 0 && threadIdx.x == 0) {
        int nz = 0;
        for (int k = 1; k <= 64; k++) {
            int idx = (N & ~1) - 2 * k + 1;
            if (idx > 0 && idx < N) nz |= batch_w[idx];
        }
        g_is64 = (nz == 0) ? 1 : 0;
    }
}

__global__ void k_count(const void* __restrict__ ei, int E, int N) {
    int e = blockIdx.x * blockDim.x + threadIdx.x;
    if (e >= E) return;
    unsigned d = (unsigned)idx_at(ei, (long long)E + e);
    if (d < (unsigned)N) atomicAdd(&g_cnt[d], 1);
}

// scan pass 1 (+ dinv)
__global__ void k_scan1(int N) {
    __shared__ int s[1024];
    int tid = threadIdx.x;
    int i = blockIdx.x * 1024 + tid;
    int v = (i < N) ? g_cnt[i] : 0;
    if (i < N) g_dinv[i] = rsqrtf((float)(v + 1));
    s[tid] = v;
    __syncthreads();
#pragma unroll
    for (int off = 1; off < 1024; off <<= 1) {
        int t = (tid >= off) ? s[tid - off] : 0;
        __syncthreads();
        s[tid] += t;
        __syncthreads();
    }
    if (i < N) g_off[i] = s[tid] - v;
    if (tid == 1023) g_bsum[blockIdx.x] = s[1023];
}

// scan pass 2+3 merged
__global__ void k_scan23(int N, int nb) {
    __shared__ int s[256];
    int tid = threadIdx.x;
    if (tid < 256) s[tid] = (tid < nb) ? g_bsum[tid] : 0;
    __syncthreads();
#pragma unroll
    for (int off = 1; off < 256; off <<= 1) {
        int t = 0;
        if (tid < 256 && tid >= off) t = s[tid - off];
        __syncthreads();
        if (tid < 256) s[tid] += t;
        __syncthreads();
    }
    int i = blockIdx.x * 1024 + tid;
    if (i < N) {
        int pre = (blockIdx.x > 0) ? s[blockIdx.x - 1] : 0;
        int o = g_off[i] + pre;
        g_off[i] = o;
        g_cur[i] = o;
    }
}

__global__ void k_bucket(const void* __restrict__ ei, int E, int N) {
    int e = blockIdx.x * blockDim.x + threadIdx.x;
    if (e >= E) return;
    unsigned s = (unsigned)idx_at(ei, e);
    unsigned d = (unsigned)idx_at(ei, (long long)E + e);
    if (s >= (unsigned)N || d >= (unsigned)N) return;
    int pos = atomicAdd(&g_cur[d], 1);
    if ((unsigned)pos >= (unsigned)E) return;
    g_esrc[pos] = (int)s;
}

// ---------------- register-blocked GEMM with packed f32x2 FMAs ----------------
// MODE 0: in = xin (fp32),   out g_h (fp32)   = relu(acc + bias_out)
// MODE 1: in = g_h (fp32),   out g_t16 (fp16) = acc * dinv[row]
// MODE 2: in = relu(g_agg16 + bias_in) (fp16 src), out g_t16 = acc * dinv[row]
template <int K, int MODE>
__global__ __launch_bounds__(256) void k_gemm(
    const float* __restrict__ xin, const float* __restrict__ W,
    const float* __restrict__ bias_in, const float* __restrict__ bias_out, int N)
{
    __shared__ float in_s[128 * 33];
    __shared__ float W_s[32 * 64];

    const int tid = threadIdx.x;
    const int l   = tid & 31;
    const int cg  = tid >> 5;
    const int rowBase = blockIdx.x * 128;

    unsigned long long acc[4][4];
#pragma unroll
    for (int i = 0; i < 4; i++)
#pragma unroll
        for (int j = 0; j < 4; j++) acc[i][j] = 0ull;

    const int NCHUNK = K / 32;
#pragma unroll
    for (int ch = 0; ch < NCHUNK; ch++) {
        if (MODE == 2) {
            // fp16 input: 128 rows x 32 cols, 8 halves (16 B) per item
            for (int idx = tid; idx < 128 * 4; idx += 256) {
                int r  = idx >> 2;
                int c8 = (idx & 3) * 8;
                int gr = rowBase + r;
                int gc = ch * 32 + c8;
                float f[8];
                if (gr < N) {
                    uint4 u = *(const uint4*)(g_agg16 + (size_t)gr * 64 + gc);
                    __half2 hp[4];
                    *(uint4*)hp = u;
#pragma unroll
                    for (int j = 0; j < 4; j++) {
                        float2 t = __half22float2(hp[j]);
                        f[j * 2] = t.x; f[j * 2 + 1] = t.y;
                    }
                } else {
#pragma unroll
                    for (int j = 0; j < 8; j++) f[j] = 0.f;
                }
#pragma unroll
                for (int j = 0; j < 8; j++)
                    f[j] = fmaxf(f[j] + __ldg(&bias_in[gc + j]), 0.f);
                float* p = &in_s[r * 33 + c8];
#pragma unroll
                for (int j = 0; j < 8; j++) p[j] = f[j];
            }
        } else {
            const float* in = (MODE == 0) ? xin : g_h;
            for (int idx = tid; idx < 128 * 8; idx += 256) {
                int r  = idx >> 3;
                int c4 = (idx & 7) * 4;
                int gr = rowBase + r;
                int gc = ch * 32 + c4;
                float4 v = make_float4(0.f, 0.f, 0.f, 0.f);
                if (gr < N) v = *(const float4*)(in + (size_t)gr * K + gc);
                float* p = &in_s[r * 33 + c4];
                p[0] = v.x; p[1] = v.y; p[2] = v.z; p[3] = v.w;
            }
        }
        for (int idx = tid; idx < 32 * 16; idx += 256) {
            int kr = idx >> 4;
            int c4 = (idx & 15) * 4;
            *(float4*)(&W_s[kr * 64 + c4]) =
                *(const float4*)(W + (size_t)(ch * 32 + kr) * 64 + c4);
        }
        __syncthreads();

#pragma unroll 8
        for (int k = 0; k < 32; k++) {
            float a0 = in_s[(l      ) * 33 + k];
            float a1 = in_s[(l + 32 ) * 33 + k];
            float a2 = in_s[(l + 64 ) * 33 + k];
            float a3 = in_s[(l + 96 ) * 33 + k];
            unsigned long long ap0 = pack2(a0, a0);
            unsigned long long ap1 = pack2(a1, a1);
            unsigned long long ap2 = pack2(a2, a2);
            unsigned long long ap3 = pack2(a3, a3);
            const ulonglong2* wp = (const ulonglong2*)(&W_s[k * 64 + cg * 8]);
            ulonglong2 wv0 = wp[0], wv1 = wp[1];
            unsigned long long w01 = wv0.x, w23 = wv0.y, w45 = wv1.x, w67 = wv1.y;
            FMA2(acc[0][0], ap0, w01); FMA2(acc[0][1], ap0, w23);
            FMA2(acc[0][2], ap0, w45); FMA2(acc[0][3], ap0, w67);
            FMA2(acc[1][0], ap1, w01); FMA2(acc[1][1], ap1, w23);
            FMA2(acc[1][2], ap1, w45); FMA2(acc[1][3], ap1, w67);
            FMA2(acc[2][0], ap2, w01); FMA2(acc[2][1], ap2, w23);
            FMA2(acc[2][2], ap2, w45); FMA2(acc[2][3], ap2, w67);
            FMA2(acc[3][0], ap3, w01); FMA2(acc[3][1], ap3, w23);
            FMA2(acc[3][2], ap3, w45); FMA2(acc[3][3], ap3, w67);
        }
        __syncthreads();
    }

#pragma unroll
    for (int i = 0; i < 4; i++) {
        int gr = rowBase + l + 32 * i;
        if (gr >= N) continue;
        float v[8];
#pragma unroll
        for (int j = 0; j < 4; j++)
            unpack2(acc[i][j], v[j * 2], v[j * 2 + 1]);
        if (MODE == 0) {
#pragma unroll
            for (int j = 0; j < 8; j++)
                v[j] = fmaxf(v[j] + __ldg(&bias_out[cg * 8 + j]), 0.f);
            float4* tp = (float4*)(g_h + (size_t)gr * 64 + cg * 8);
            tp[0] = make_float4(v[0], v[1], v[2], v[3]);
            tp[1] = make_float4(v[4], v[5], v[6], v[7]);
        } else {
            float dv = __ldg(&g_dinv[gr]);
            __half2 hh[4];
#pragma unroll
            for (int j = 0; j < 4; j++)
                hh[j] = __floats2half2_rn(v[j * 2] * dv, v[j * 2 + 1] * dv);
            *(uint4*)(g_t16 + (size_t)gr * 64 + cg * 8) = *(uint4*)hh;
        }
    }
}

// ---------------- CSR gather-aggregate (fp16 payload, fp32 accumulate) ----------------
// 8 lanes per node; each lane owns 8 features (one uint4 = 16 B of halves).
// agg[n] = dinv[n] * ( t'[n] + sum_e t'[src_e] )
template <bool FINAL>
__global__ __launch_bounds__(256) void k_agg(
    int N, int E,
    const float* __restrict__ b2, const float* __restrict__ W_tgt,
    const float* __restrict__ b_tgt, float* out_tgt, float* hdst)
{
    int gt = blockIdx.x * blockDim.x + threadIdx.x;
    int n = gt >> 3;
    int lane = gt & 7;       // 8 lanes per node
    if (n >= N) return;

    const uint4* t4 = (const uint4*)g_t16;   // row = 8 uint4

    float2 acc[4];
#pragma unroll
    for (int j = 0; j < 4; j++) acc[j] = make_float2(0.f, 0.f);
    acc_half8(acc, __ldg(t4 + (size_t)n * 8 + lane));   // self term

    int beg = __ldg(&g_off[n]);
    int end = beg + __ldg(&g_cnt[n]);
    if (beg < 0) beg = 0;
    if (end > E) end = E;

    int e = beg;
    for (; e + 7 < end; e += 8) {
        unsigned s0 = (unsigned)__ldg(&g_esrc[e]);
        unsigned s1 = (unsigned)__ldg(&g_esrc[e + 1]);
        unsigned s2 = (unsigned)__ldg(&g_esrc[e + 2]);
        unsigned s3 = (unsigned)__ldg(&g_esrc[e + 3]);
        unsigned s4 = (unsigned)__ldg(&g_esrc[e + 4]);
        unsigned s5 = (unsigned)__ldg(&g_esrc[e + 5]);
        unsigned s6 = (unsigned)__ldg(&g_esrc[e + 6]);
        unsigned s7 = (unsigned)__ldg(&g_esrc[e + 7]);
        uint4 u0 = __ldg(t4 + (size_t)s0 * 8 + lane);
        uint4 u1 = __ldg(t4 + (size_t)s1 * 8 + lane);
        uint4 u2 = __ldg(t4 + (size_t)s2 * 8 + lane);
        uint4 u3 = __ldg(t4 + (size_t)s3 * 8 + lane);
        uint4 u4 = __ldg(t4 + (size_t)s4 * 8 + lane);
        uint4 u5 = __ldg(t4 + (size_t)s5 * 8 + lane);
        uint4 u6 = __ldg(t4 + (size_t)s6 * 8 + lane);
        uint4 u7 = __ldg(t4 + (size_t)s7 * 8 + lane);
        acc_half8(acc, u0); acc_half8(acc, u1);
        acc_half8(acc, u2); acc_half8(acc, u3);
        acc_half8(acc, u4); acc_half8(acc, u5);
        acc_half8(acc, u6); acc_half8(acc, u7);
    }
    for (; e < end; e++) {
        unsigned s0 = (unsigned)__ldg(&g_esrc[e]);
        acc_half8(acc, __ldg(t4 + (size_t)s0 * 8 + lane));
    }

    float dv = __ldg(&g_dinv[n]);
#pragma unroll
    for (int j = 0; j < 4; j++) { acc[j].x *= dv; acc[j].y *= dv; }

    if (!FINAL) {
        __half2 hh[4];
#pragma unroll
        for (int j = 0; j < 4; j++)
            hh[j] = __floats2half2_rn(acc[j].x, acc[j].y);
        *(uint4*)(g_agg16 + (size_t)n * 64 + lane * 8) = *(uint4*)hh;
    } else {
        const float4* b4 = (const float4*)b2;
        float4 ba = __ldg(b4 + lane * 2);
        float4 bb = __ldg(b4 + lane * 2 + 1);
        float h0 = fmaxf(acc[0].x + ba.x, 0.f);
        float h1 = fmaxf(acc[0].y + ba.y, 0.f);
        float h2 = fmaxf(acc[1].x + ba.z, 0.f);
        float h3 = fmaxf(acc[1].y + ba.w, 0.f);
        float h4 = fmaxf(acc[2].x + bb.x, 0.f);
        float h5 = fmaxf(acc[2].y + bb.y, 0.f);
        float h6 = fmaxf(acc[3].x + bb.z, 0.f);
        float h7 = fmaxf(acc[3].y + bb.w, 0.f);
        float4* hp = (float4*)(hdst + (size_t)n * 64 + lane * 8);
        hp[0] = make_float4(h0, h1, h2, h3);
        hp[1] = make_float4(h4, h5, h6, h7);
        if (out_tgt) {
            const float4* w4 = (const float4*)W_tgt;
            float4 wa = __ldg(w4 + lane * 2);
            float4 wb = __ldg(w4 + lane * 2 + 1);
            float p = h0 * wa.x + h1 * wa.y + h2 * wa.z + h3 * wa.w
                    + h4 * wb.x + h5 * wb.y + h6 * wb.z + h7 * wb.w;
#pragma unroll
            for (int off = 4; off > 0; off >>= 1)
                p += __shfl_down_sync(0xffffffffu, p, off, 8);
            if (lane == 0) out_tgt[n] = p + __ldg(b_tgt);
        }
    }
}

// ---------------- pooling + graph heads; graph bounds via binary search ----------------
__global__ __launch_bounds__(256) void k_logits(
    const void* __restrict__ batch, const float* __restrict__ hsrc,
    const float* __restrict__ W_act, const float* __restrict__ b_act,
    const float* __restrict__ W_atom, const float* __restrict__ b_atom,
    float* out_act, float* out_atom, int N)
{
    int g = blockIdx.x;
    int tid = threadIdx.x;
    int f = tid & 63;
    int sl = tid >> 6;
    __shared__ int bounds[2];
    __shared__ float red[4][64];
    __shared__ float p[64];

    if (tid < 2) {
        int target = g + tid;
        int lo = 0, hi = N;
        while (lo < hi) {
            int mid = (lo + hi) >> 1;
            if (idx_at(batch, mid) < target) lo = mid + 1; else hi = mid;
        }
        bounds[tid] = lo;
    }
    __syncthreads();
    int s0 = bounds[0], s1 = bounds[1];

    float acc = 0.f;
    for (int i = s0 + sl; i < s1; i += 4)
        acc += __ldg(&hsrc[(size_t)i * 64 + f]);
    red[sl][f] = acc;
    __syncthreads();

    if (tid < 64) {
        int c = s1 - s0;
        float total = red[0][f] + red[1][f] + red[2][f] + red[3][f];
        p[f] = (c > 0) ? total / (float)c : 0.0f;
    }
    __syncthreads();

    if (tid < 8) {
        if (out_act) {
            float s = __ldg(&b_act[tid]);
#pragma unroll 8
            for (int k = 0; k < 64; k++) s += p[k] * __ldg(&W_act[k * 8 + tid]);
            out_act[g * 8 + tid] = s;
        }
    } else if (tid < 24) {
        if (out_atom) {
            int jj = tid - 8;
            float s = __ldg(&b_atom[jj]);
#pragma unroll 8
            for (int k = 0; k < 64; k++) s += p[k] * __ldg(&W_atom[k * 16 + jj]);
            out_atom[g * 16 + jj] = s;
        }
    }
}

// ---------------- launch ----------------
extern "C" void kernel_launch(void* const* d_in, const int* in_sizes, int n_in,
                              void* d_out, int out_size)
{
    const float* x       = (const float*)d_in[0];
    const void*  ei      = d_in[1];
    const void*  batch   = d_in[2];
    const float* W_emb   = (const float*)d_in[3];
    const float* b_emb   = (const float*)d_in[4];
    const float* W_convs = (const float*)d_in[5];
    const float* b_convs = (const float*)d_in[6];
    const float* W_act   = (const float*)d_in[7];
    const float* b_act   = (const float*)d_in[8];
    const float* W_tgt   = (const float*)d_in[9];
    const float* b_tgt   = (const float*)d_in[10];
    const float* W_atom  = (const float*)d_in[11];
    const float* b_atom  = (const float*)d_in[12];

    const int N = in_sizes[0] / 32;
    int E = in_sizes[1] / 2;
    if (E > MAXE) E = MAXE;

    const long long szA = (long long)NGRAPH * 8;
    const long long szT = N;
    const long long szM = (long long)NGRAPH * 16;
    const long long szH = (long long)N * 64;

    float* out = (float*)d_out;
    long long cum = 0;
    float* out_act  = nullptr;
    float* out_tgt  = nullptr;
    float* out_atom = nullptr;
    float* out_h    = nullptr;
    if (cum + szA <= out_size) { out_act  = out + cum; cum += szA; }
    if (cum + szT <= out_size) { out_tgt  = out + cum; cum += szT; }
    if (cum + szM <= out_size) { out_atom = out + cum; cum += szM; }
    if (cum + szH <= out_size) { out_h    = out + cum; cum += szH; }

    float* hdst;
    {
        static float* g_hout_ptr = nullptr;
        if (!g_hout_ptr) cudaGetSymbolAddress((void**)&g_hout_ptr, g_hout);
        // float4 stores need 16-B alignment of out_h; fall back if misaligned
        hdst = (out_h && ((((uintptr_t)out_h) & 15) == 0)) ? out_h : g_hout_ptr;
    }

    const int TB = 256;
    const int gN   = (N + TB - 1) / TB;
    const int gE   = (E + TB - 1) / TB;
    const int gRow = (N + 127) / 128;
    const int gN8  = (int)(((long long)N * 8 + TB - 1) / TB);
    const int nb   = (N + 1023) / 1024;

    static cudaStream_t s1 = nullptr;
    static cudaEvent_t evFork = nullptr, evDinv = nullptr, evGemm = nullptr;
    static int streamsOk = -1;
    if (streamsOk < 0) {
        bool ok = (cudaStreamCreateWithFlags(&s1, cudaStreamNonBlocking) == cudaSuccess)
               && (cudaEventCreateWithFlags(&evFork, cudaEventDisableTiming) == cudaSuccess)
               && (cudaEventCreateWithFlags(&evDinv, cudaEventDisableTiming) == cudaSuccess)
               && (cudaEventCreateWithFlags(&evGemm, cudaEventDisableTiming) == cudaSuccess);
        streamsOk = ok ? 1 : 0;
    }

    if (streamsOk) {
        cudaEventRecord(evFork, 0);
        cudaStreamWaitEvent(s1, evFork, 0);
        k_gemm<32, 0><<<gRow, TB, 0, s1>>>(x, W_emb, nullptr, b_emb, N);

        k_prep<<<gN, TB>>>((const int*)batch, N);
        k_count<<<gE, TB>>>(ei, E, N);
        k_scan1<<<nb, 1024>>>(N);
        cudaEventRecord(evDinv, 0);

        cudaStreamWaitEvent(s1, evDinv, 0);
        k_gemm<64, 1><<<gRow, TB, 0, s1>>>(nullptr, W_convs + 0 * 4096, nullptr, nullptr, N);
        cudaEventRecord(evGemm, s1);

        k_scan23<<<nb, 1024>>>(N, nb);
        k_bucket<<<gE, TB>>>(ei, E, N);

        cudaStreamWaitEvent(0, evGemm, 0);
    } else {
        k_prep<<<gN, TB>>>((const int*)batch, N);
        k_count<<<gE, TB>>>(ei, E, N);
        k_scan1<<<nb, 1024>>>(N);
        k_scan23<<<nb, 1024>>>(N, nb);
        k_bucket<<<gE, TB>>>(ei, E, N);
        k_gemm<32, 0><<<gRow, TB>>>(x, W_emb, nullptr, b_emb, N);
        k_gemm<64, 1><<<gRow, TB>>>(nullptr, W_convs + 0 * 4096, nullptr, nullptr, N);
    }

    k_agg<false><<<gN8, TB>>>(N, E, nullptr, nullptr, nullptr, nullptr, nullptr);

    k_gemm<64, 2><<<gRow, TB>>>(nullptr, W_convs + 1 * 4096, b_convs + 0 * 64, nullptr, N);
    k_agg<false><<<gN8, TB>>>(N, E, nullptr, nullptr, nullptr, nullptr, nullptr);

    k_gemm<64, 2><<<gRow, TB>>>(nullptr, W_convs + 2 * 4096, b_convs + 1 * 64, nullptr, N);
    k_agg<true><<<gN8, TB>>>(N, E, b_convs + 2 * 64, W_tgt, b_tgt, out_tgt, hdst);

    k_logits<<<NGRAPH, TB>>>(batch, hdst, W_act, b_act, W_atom, b_atom, out_act, out_atom, N);

    if (hdst != out_h && out_h) {
        cudaMemcpyAsync(out_h, hdst, (size_t)N * 64 * sizeof(float),
                        cudaMemcpyDeviceToDevice, 0);
    }
}